// round 6
// baseline (speedup 1.0000x reference)
#include <cuda_runtime.h>
#include <cstdint>

// ---------------------------------------------------------------------------
// Problem constants
// ---------------------------------------------------------------------------
#define KK 16
#define YY 32
#define CC 16
#define NBUCKET (KK * YY)          // 512
#define ACC_ELEMS (NBUCKET * CC)   // 8192
#define ACC_F4 (ACC_ELEMS / 4)     // 2048 float4 slots
#define NREP 32                    // accumulator replicas
#define EPS_F 1e-8f

#define GRIDB 1184                 // 148 SMs x 8 CTAs
#define TPB 256

// Replicated scratch accumulator: 32 * 8192 f32 = 1 MB. Zeroed at module load;
// the finalize phase resets it after reading, so every launch (and every graph
// replay) enters with it zeroed. 16B-aligned: both red.v4 and the float4
// replica-reduce loads require it.
__device__ __align__(16) float g_acc[NREP * ACC_ELEMS];
__device__ unsigned int g_done = 0;

__device__ __forceinline__ void red_v4(float* dst, float4 v) {
    asm volatile("red.global.add.v4.f32 [%0], {%1, %2, %3, %4};"
                 :: "l"(dst), "f"(v.x), "f"(v.y), "f"(v.z), "f"(v.w)
                 : "memory");
}

// ---------------------------------------------------------------------------
// Fused kernel: scatter-add + (last block) replica-reduce, normalize, reset.
// ---------------------------------------------------------------------------
__global__ void __launch_bounds__(TPB, 8)
cc_fused(const int* __restrict__ xl,
         const int* __restrict__ yl,
         const float4* __restrict__ post,   // [N rows][4 float4]
         float* __restrict__ out,           // [16,32,16]
         int n_f4) {
    const int T = GRIDB * TPB;                         // total threads
    const int g = blockIdx.x * TPB + threadIdx.x;
    float* rep = &g_acc[(blockIdx.x & (NREP - 1)) * ACC_ELEMS];

    // ---- phase 1: scatter (grid-stride, 4x unrolled for MLP) ----
    for (int i = g; i < n_f4; i += 4 * T) {
        int i1 = i + T, i2 = i + 2 * T, i3 = i + 3 * T;
        bool p1 = i1 < n_f4, p2 = i2 < n_f4, p3 = i3 < n_f4;

        // batch all loads first (independent -> MLP)
        float4 v0 = __ldcs(&post[i]);
        float4 v1, v2, v3;
        int r0 = i >> 2, r1 = i1 >> 2, r2 = i2 >> 2, r3 = i3 >> 2;
        int b0 = xl[r0] * YY + yl[r0];
        int b1 = 0, b2 = 0, b3 = 0;
        if (p1) { v1 = __ldcs(&post[i1]); b1 = xl[r1] * YY + yl[r1]; }
        if (p2) { v2 = __ldcs(&post[i2]); b2 = xl[r2] * YY + yl[r2]; }
        if (p3) { v3 = __ldcs(&post[i3]); b3 = xl[r3] * YY + yl[r3]; }

        red_v4(&rep[b0 * CC + (i & 3) * 4], v0);
        if (p1) red_v4(&rep[b1 * CC + (i1 & 3) * 4], v1);
        if (p2) red_v4(&rep[b2 * CC + (i2 & 3) * 4], v2);
        if (p3) red_v4(&rep[b3 * CC + (i3 & 3) * 4], v3);
    }

    // ---- grid-wide completion: last block finalizes ----
    __threadfence();                 // make REDs visible device-wide
    __syncthreads();
    __shared__ unsigned int s_last;
    if (threadIdx.x == 0) {
        unsigned int t = atomicAdd(&g_done, 1u);
        s_last = (t == GRIDB - 1) ? 1u : 0u;
    }
    __syncthreads();
    if (!s_last) return;
    __threadfence();                 // acquire side

    // ---- phase 2 (last block only): reduce replicas into smem ----
    __shared__ __align__(16) float red[ACC_ELEMS];    // 32 KB
    float4* accv = (float4*)g_acc;
    float4* redv = (float4*)red;
    for (int s = threadIdx.x; s < ACC_F4; s += TPB) {
        float4 a = make_float4(0.f, 0.f, 0.f, 0.f);
#pragma unroll
        for (int r = 0; r < NREP; r++) {
            float4 v = accv[r * ACC_F4 + s];
            a.x += v.x; a.y += v.y; a.z += v.z; a.w += v.w;
        }
        redv[s] = a;
    }
    __syncthreads();

    // ---- phase 3: add eps, normalize over Y ----
    {
        int t = threadIdx.x;          // 0..255 = (k, c)
        int k = t >> 4;
        int c = t & 15;
        float vals[YY];
        float s = 0.0f;
#pragma unroll
        for (int y = 0; y < YY; y++) {
            float v = red[(k * YY + y) * CC + c] + EPS_F;
            vals[y] = v;
            s += v;
        }
        float inv = 1.0f / s;
#pragma unroll
        for (int y = 0; y < YY; y++)
            out[(k * YY + y) * CC + c] = vals[y] * inv;
    }

    // reset accumulator + counter for the next launch / graph replay
    float4 z = make_float4(0.f, 0.f, 0.f, 0.f);
    for (int s = threadIdx.x; s < NREP * ACC_F4; s += TPB)
        accv[s] = z;
    if (threadIdx.x == 0) g_done = 0;
}

// ---------------------------------------------------------------------------
// Launch
// ---------------------------------------------------------------------------
extern "C" void kernel_launch(void* const* d_in, const int* in_sizes, int n_in,
                              void* d_out, int out_size) {
    const int*    xl   = (const int*)d_in[0];        // x_labels [N] int32
    const int*    yl   = (const int*)d_in[1];        // y_labels [N] int32
    const float4* post = (const float4*)d_in[2];     // posterior [N,16] f32
    float* out = (float*)d_out;                      // [16,32,16] f32

    int n = in_sizes[0];
    int n_f4 = n * (CC / 4);

    cc_fused<<<GRIDB, TPB>>>(xl, yl, post, out, n_f4);
}

// round 8
// speedup vs baseline: 1.3846x; 1.3846x over previous
#include <cuda_runtime.h>
#include <cstdint>

// ---------------------------------------------------------------------------
// Problem constants
// ---------------------------------------------------------------------------
#define KK 16
#define YY 32
#define CC 16
#define NBUCKET (KK * YY)          // 512
#define ACC_ELEMS (NBUCKET * CC)   // 8192
#define ACC_F4 (ACC_ELEMS / 4)     // 2048
#define NREP 32                    // accumulator replicas
#define EPS_F 1e-8f

#define SGRID 1184                 // 148 SMs x 8 CTAs x 256 thr = exactly full residency
#define TPB 256

// Replicated scratch: 32 x 8192 f32 = 1 MB. Zero-initialized at module load;
// cc_finalize resets it after reading, so every subsequent launch (and every
// graph replay) enters with it zeroed. 16B-aligned for red.v4 / float4 access.
__device__ __align__(16) float g_acc[NREP * ACC_ELEMS];

// ---------------------------------------------------------------------------
// Kernel 1: scatter-add. One thread per float4 (quarter-row), fully coalesced
// 16B loads; 4 lanes share a row's labels (coalesced LDG.b32).
// red.global.add.v4.f32 -> L2-side reduction. NO smem, NO extra state:
// this kernel's occupancy and issue path stay pristine.
// ---------------------------------------------------------------------------
__global__ void __launch_bounds__(TPB)
cc_scatter(const int* __restrict__ xl,
           const int* __restrict__ yl,
           const float4* __restrict__ post,
           int n_f4) {
    int stride = gridDim.x * blockDim.x;
    float* rep = &g_acc[(blockIdx.x & (NREP - 1)) * ACC_ELEMS];
    for (int i = blockIdx.x * blockDim.x + threadIdx.x; i < n_f4; i += stride) {
        int row = i >> 2;
        int c4  = i & 3;
        float4 v = post[i];
        int b = xl[row] * YY + yl[row];              // bucket in [0,512)
        float* dst = &rep[b * CC + c4 * 4];
        asm volatile("red.global.add.v4.f32 [%0], {%1, %2, %3, %4};"
                     :: "l"(dst), "f"(v.x), "f"(v.y), "f"(v.z), "f"(v.w)
                     : "memory");
    }
}

// ---------------------------------------------------------------------------
// Kernel 2: finalize. Reduce replicas -> smem, add eps, normalize over Y,
// then RESET g_acc so the next launch/replay starts from zero.
// ---------------------------------------------------------------------------
__global__ void cc_finalize(float* __restrict__ out) {
    __shared__ __align__(16) float red[ACC_ELEMS];   // 32 KB
    int tid = threadIdx.x;   // 0..511

    float4* accv = (float4*)g_acc;
    float4* redv = (float4*)red;
    for (int s = tid; s < ACC_F4; s += 512) {
        float4 a = make_float4(0.f, 0.f, 0.f, 0.f);
#pragma unroll
        for (int r = 0; r < NREP; r++) {
            float4 v = accv[r * ACC_F4 + s];
            a.x += v.x; a.y += v.y; a.z += v.z; a.w += v.w;
        }
        redv[s] = a;
    }
    __syncthreads();

    if (tid < KK * CC) {
        int k = tid >> 4;
        int c = tid & 15;
        float vals[YY];
        float s = 0.0f;
#pragma unroll
        for (int y = 0; y < YY; y++) {
            float v = red[(k * YY + y) * CC + c] + EPS_F;
            vals[y] = v;
            s += v;
        }
        float inv = 1.0f / s;
#pragma unroll
        for (int y = 0; y < YY; y++)
            out[(k * YY + y) * CC + c] = vals[y] * inv;
    }

    // Reset scratch for the next launch / graph replay (1 MB of STG.128).
    float4 z = make_float4(0.f, 0.f, 0.f, 0.f);
    for (int s = tid; s < NREP * ACC_F4; s += 512)
        accv[s] = z;
}

// ---------------------------------------------------------------------------
// Launch
// ---------------------------------------------------------------------------
extern "C" void kernel_launch(void* const* d_in, const int* in_sizes, int n_in,
                              void* d_out, int out_size) {
    const int*    xl   = (const int*)d_in[0];        // x_labels [N] int32
    const int*    yl   = (const int*)d_in[1];        // y_labels [N] int32
    const float4* post = (const float4*)d_in[2];     // posterior [N,16] f32
    float* out = (float*)d_out;                      // [16,32,16] f32

    int n = in_sizes[0];
    int n_f4 = n * (CC / 4);

    cc_scatter<<<SGRID, TPB>>>(xl, yl, post, n_f4);
    cc_finalize<<<1, 512>>>(out);
}

// round 9
// speedup vs baseline: 1.8246x; 1.3178x over previous
#include <cuda_runtime.h>
#include <cstdint>

// ---------------------------------------------------------------------------
// Problem constants
// ---------------------------------------------------------------------------
#define KK 16
#define YY 32
#define CC 16
#define NBUCKET (KK * YY)          // 512
#define ACC_ELEMS (NBUCKET * CC)   // 8192
#define NREP 32                    // accumulator replicas
#define EPS_F 1e-8f

#define SGRID 1184                 // 148 SMs x 8 CTAs x 256 thr = exact full residency
#define TPB 256

// Replicated scratch: 32 x 8192 f32 = 1 MB. Zero-initialized at module load;
// cc_finalize resets it after reading, so every subsequent launch (and every
// graph replay) enters with it zeroed. 16B-aligned for red.v4.
__device__ __align__(16) float g_acc[NREP * ACC_ELEMS];

// ---------------------------------------------------------------------------
// Kernel 1: scatter-add (UNCHANGED from round 8 — measured ~70us).
// One thread per float4 (quarter-row), coalesced 16B loads, red.global.add.v4
// into this CTA's replica. No smem, no extra state.
// ---------------------------------------------------------------------------
__global__ void __launch_bounds__(TPB)
cc_scatter(const int* __restrict__ xl,
           const int* __restrict__ yl,
           const float4* __restrict__ post,
           int n_f4) {
    int stride = gridDim.x * blockDim.x;
    float* rep = &g_acc[(blockIdx.x & (NREP - 1)) * ACC_ELEMS];
    for (int i = blockIdx.x * blockDim.x + threadIdx.x; i < n_f4; i += stride) {
        int row = i >> 2;
        int c4  = i & 3;
        float4 v = post[i];
        int b = xl[row] * YY + yl[row];              // bucket in [0,512)
        float* dst = &rep[b * CC + c4 * 4];
        asm volatile("red.global.add.v4.f32 [%0], {%1, %2, %3, %4};"
                     :: "l"(dst), "f"(v.x), "f"(v.y), "f"(v.z), "f"(v.w)
                     : "memory");
    }
}

// ---------------------------------------------------------------------------
// Kernel 2: finalize — PARALLEL epilogue. 16 blocks (one per k), 512 threads
// (one per (y,c) element of that k-slice). Each thread:
//   - sums its element across 32 replicas (32 independent loads, MLP=32)
//   - participates in the Y-sum for its channel via smem
//   - writes normalized output
//   - zeroes its 32 replica slots (disjoint across blocks -> race-free)
// ---------------------------------------------------------------------------
__global__ void __launch_bounds__(512)
cc_finalize(float* __restrict__ out) {
    __shared__ float s_val[YY * CC];     // per-(y,c) numerator
    __shared__ float s_inv[CC];          // per-channel reciprocal denominator

    int k   = blockIdx.x;                // 0..15
    int tid = threadIdx.x;               // 0..511
    int y   = tid >> 4;
    int c   = tid & 15;
    int elem = (k * YY + y) * CC + c;

    // replica-sum (32 independent global loads)
    float s = 0.0f;
#pragma unroll
    for (int r = 0; r < NREP; r++)
        s += g_acc[r * ACC_ELEMS + elem];
    float v = s + EPS_F;
    s_val[tid] = v;
    __syncthreads();

    // denominator: sum over Y per channel (16 threads, 32 adds each)
    if (tid < CC) {
        float d = 0.0f;
#pragma unroll
        for (int yy = 0; yy < YY; yy++)
            d += s_val[yy * CC + tid];
        s_inv[tid] = 1.0f / d;
    }
    __syncthreads();

    out[elem] = v * s_inv[c];

    // reset this element's replica slots for the next launch / graph replay
#pragma unroll
    for (int r = 0; r < NREP; r++)
        g_acc[r * ACC_ELEMS + elem] = 0.0f;
}

// ---------------------------------------------------------------------------
// Launch
// ---------------------------------------------------------------------------
extern "C" void kernel_launch(void* const* d_in, const int* in_sizes, int n_in,
                              void* d_out, int out_size) {
    const int*    xl   = (const int*)d_in[0];        // x_labels [N] int32
    const int*    yl   = (const int*)d_in[1];        // y_labels [N] int32
    const float4* post = (const float4*)d_in[2];     // posterior [N,16] f32
    float* out = (float*)d_out;                      // [16,32,16] f32

    int n = in_sizes[0];
    int n_f4 = n * (CC / 4);

    cc_scatter<<<SGRID, TPB>>>(xl, yl, post, n_f4);
    cc_finalize<<<KK, 512>>>(out);
}